// round 5
// baseline (speedup 1.0000x reference)
#include <cuda_runtime.h>
#include <cstdint>

#define B_  8
#define C_  19
#define H_  512
#define W_  512
#define PLANE (H_*W_)          // 262144
#define BC (B_*C_)             // 152

// adjusted: [B,C,64,64]
__device__ float g_adjusted[BC * 64 * 64];

// ---------------------------------------------------------------------------
// Kernel 1 (unchanged from R4): argmax over C=19 + 8x8 histogram /64.
// ---------------------------------------------------------------------------
__global__ __launch_bounds__(256) void argmax_pool_kernel(const float* __restrict__ x)
{
    const int strip = blockIdx.x;
    const int b     = blockIdx.y;
    const int t     = threadIdx.x;
    const int cq    = t & 127;
    const int rh    = t >> 7;

    __shared__ int hist[64][20];
    for (int i = t; i < 64 * 20; i += 256) ((int*)hist)[i] = 0;
    __syncthreads();

    const float* xb = x + (size_t)b * C_ * PLANE
                        + ((size_t)strip * 8 + rh * 4) * W_ + cq * 4;
    const int blk = cq >> 1;

    #pragma unroll
    for (int r = 0; r < 4; r++) {
        const float* row = xb + r * W_;
        float4 bv = __ldcs((const float4*)row);
        int bx = 0, by = 0, bz = 0, bw = 0;
        #pragma unroll
        for (int c = 1; c < C_; c++) {
            float4 v = __ldcs((const float4*)(row + (size_t)c * PLANE));
            if (v.x > bv.x) { bv.x = v.x; bx = c; }
            if (v.y > bv.y) { bv.y = v.y; by = c; }
            if (v.z > bv.z) { bv.z = v.z; bz = c; }
            if (v.w > bv.w) { bv.w = v.w; bw = c; }
        }
        atomicAdd(&hist[blk][bx], 1);
        atomicAdd(&hist[blk][by], 1);
        atomicAdd(&hist[blk][bz], 1);
        atomicAdd(&hist[blk][bw], 1);
    }
    __syncthreads();

    for (int i = t; i < 64 * C_; i += 256) {
        int j = i / C_, c = i % C_;
        g_adjusted[((size_t)(b * C_ + c) * 64 + strip) * 64 + j] =
            (float)hist[j][c] * (1.0f / 64.0f);
    }
}

// ---------------------------------------------------------------------------
// Kernel 2: hybrid patch storage. l=0..7 in registers (32 regs), l=8..15 in
// padded smem (stride 80 floats -> conflict-free LDS.128). 4 CTAs/SM.
// Depth-1 prefetch (R2 config, measured best).
// ---------------------------------------------------------------------------
#define CPP 8
#define TPC 128
#define PSTR 80                // smem patch row stride (floats); 320B == 64 mod 128

__global__ __launch_bounds__(256, 4) void modulate_kernel(
    const float* __restrict__ x,
    const float* __restrict__ attn,
    float* __restrict__ out_y,
    float* __restrict__ out_c)
{
    const int bc   = blockIdx.x >> 3;      // 0..151
    const int q    = blockIdx.x & 7;
    const int tid  = threadIdx.x;
    const int mgrp = tid >> 6;             // 0..3
    const int quad = tid & 63;
    const int py   = quad >> 2;            // 0..15
    const int px0  = (quad & 3) << 2;      // 0,4,8,12

    __shared__ float4 sm_attn[TPC * 4];            // 8KB
    __shared__ float  sm_patch[32 * PSTR];         // rows 32..63 of adjusted, 10KB

    const float* adjc = g_adjusted + (size_t)bc * 4096;

    // l = 0..7 (pi = 0,1) in registers
    float4 pr[8];
    #pragma unroll
    for (int pi = 0; pi < 2; pi++)
        #pragma unroll
        for (int pj = 0; pj < 4; pj++)
            pr[pi * 4 + pj] =
                *(const float4*)(adjc + (pi * 16 + py) * 64 + pj * 16 + px0);

    // stage attn rows (this CTA's 128 tiles)
    const float4* src = (const float4*)(attn + (size_t)bc * 1024 * 16) + q * TPC * 4;
    for (int i = tid; i < TPC * 4; i += 256) sm_attn[i] = src[i];

    // stage adjusted rows 32..63 into padded smem (pi = 2,3)
    for (int i = tid; i < 32 * 16; i += 256) {
        int r = i >> 4, cq4 = i & 15;
        *(float4*)(sm_patch + r * PSTR + cq4 * 4) =
            *(const float4*)(adjc + (32 + r) * 64 + cq4 * 4);
    }
    __syncthreads();

    const float* xp = x + (size_t)bc * PLANE;
    float*       yp = out_y + (size_t)bc * PLANE;
    float*       cp = out_c + (size_t)bc * PLANE;

    const int mh = q * 4 + mgrp;
    const int h  = mh * 16 + py;
    const size_t base = (size_t)h * W_ + px0;
    const int mlbase = mgrp * 32;

    // per-thread loop-invariant smem patch base (pi=2 block)
    const float* sp = sm_patch + py * PSTR + px0;

    float4 xv = __ldcs((const float4*)(xp + base));   // prefetch i=0

    #pragma unroll 1
    for (int i = 0; i < 32; i++) {
        const size_t pix = base + (size_t)i * 16;
        const float4 cur = xv;
        if (i < 31)
            xv = __ldcs((const float4*)(xp + pix + 16));

        float4 c4 = make_float4(0.f, 0.f, 0.f, 0.f);
        const int mloc = mlbase + i;

        // l = 0..7 from registers
        #pragma unroll
        for (int g = 0; g < 2; g++) {
            float4 a4 = sm_attn[mloc * 4 + g];
            c4.x = fmaf(a4.x, pr[g*4+0].x, c4.x);
            c4.y = fmaf(a4.x, pr[g*4+0].y, c4.y);
            c4.z = fmaf(a4.x, pr[g*4+0].z, c4.z);
            c4.w = fmaf(a4.x, pr[g*4+0].w, c4.w);
            c4.x = fmaf(a4.y, pr[g*4+1].x, c4.x);
            c4.y = fmaf(a4.y, pr[g*4+1].y, c4.y);
            c4.z = fmaf(a4.y, pr[g*4+1].z, c4.z);
            c4.w = fmaf(a4.y, pr[g*4+1].w, c4.w);
            c4.x = fmaf(a4.z, pr[g*4+2].x, c4.x);
            c4.y = fmaf(a4.z, pr[g*4+2].y, c4.y);
            c4.z = fmaf(a4.z, pr[g*4+2].z, c4.z);
            c4.w = fmaf(a4.z, pr[g*4+2].w, c4.w);
            c4.x = fmaf(a4.w, pr[g*4+3].x, c4.x);
            c4.y = fmaf(a4.w, pr[g*4+3].y, c4.y);
            c4.z = fmaf(a4.w, pr[g*4+3].z, c4.z);
            c4.w = fmaf(a4.w, pr[g*4+3].w, c4.w);
        }

        // l = 8..15 from padded smem
        #pragma unroll
        for (int g = 2; g < 4; g++) {
            float4 a4 = sm_attn[mloc * 4 + g];
            const float* spg = sp + (g - 2) * 16 * PSTR;
            #pragma unroll
            for (int pj = 0; pj < 4; pj++) {
                float4 pv = *(const float4*)(spg + pj * 16);
                float av = (pj == 0) ? a4.x : (pj == 1) ? a4.y : (pj == 2) ? a4.z : a4.w;
                c4.x = fmaf(av, pv.x, c4.x);
                c4.y = fmaf(av, pv.y, c4.y);
                c4.z = fmaf(av, pv.z, c4.z);
                c4.w = fmaf(av, pv.w, c4.w);
            }
        }

        float4 y2;
        float tx = 1.f + c4.x; y2.x = cur.x * tx * tx;
        float ty = 1.f + c4.y; y2.y = cur.y * ty * ty;
        float tz = 1.f + c4.z; y2.z = cur.z * tz * tz;
        float tw = 1.f + c4.w; y2.w = cur.w * tw * tw;

        __stcs((float4*)(yp + pix), y2);
        __stcs((float4*)(cp + pix), c4);
    }
}

extern "C" void kernel_launch(void* const* d_in, const int* in_sizes, int n_in,
                              void* d_out, int out_size)
{
    const float* x    = (const float*)d_in[0];
    const float* attn = (const float*)d_in[1];
    float* out_y = (float*)d_out;
    float* out_c = (float*)d_out + (size_t)BC * PLANE;

    dim3 g1(64, 8);
    argmax_pool_kernel<<<g1, 256>>>(x);
    modulate_kernel<<<BC * CPP, 256>>>(x, attn, out_y, out_c);
}

// round 6
// speedup vs baseline: 1.4418x; 1.4418x over previous
#include <cuda_runtime.h>
#include <cstdint>

#define B_  8
#define C_  19
#define H_  512
#define W_  512
#define PLANE (H_*W_)          // 262144
#define BC (B_*C_)             // 152

// adjusted: [B,C,64,64]
__device__ float g_adjusted[BC * 64 * 64];

// ---------------------------------------------------------------------------
// Kernel 1 (unchanged): argmax over C=19 + 8x8 histogram /64.
// ---------------------------------------------------------------------------
__global__ __launch_bounds__(256) void argmax_pool_kernel(const float* __restrict__ x)
{
    const int strip = blockIdx.x;
    const int b     = blockIdx.y;
    const int t     = threadIdx.x;
    const int cq    = t & 127;
    const int rh    = t >> 7;

    __shared__ int hist[64][20];
    for (int i = t; i < 64 * 20; i += 256) ((int*)hist)[i] = 0;
    __syncthreads();

    const float* xb = x + (size_t)b * C_ * PLANE
                        + ((size_t)strip * 8 + rh * 4) * W_ + cq * 4;
    const int blk = cq >> 1;

    #pragma unroll
    for (int r = 0; r < 4; r++) {
        const float* row = xb + r * W_;
        float4 bv = __ldcs((const float4*)row);
        int bx = 0, by = 0, bz = 0, bw = 0;
        #pragma unroll
        for (int c = 1; c < C_; c++) {
            float4 v = __ldcs((const float4*)(row + (size_t)c * PLANE));
            if (v.x > bv.x) { bv.x = v.x; bx = c; }
            if (v.y > bv.y) { bv.y = v.y; by = c; }
            if (v.z > bv.z) { bv.z = v.z; bz = c; }
            if (v.w > bv.w) { bv.w = v.w; bw = c; }
        }
        atomicAdd(&hist[blk][bx], 1);
        atomicAdd(&hist[blk][by], 1);
        atomicAdd(&hist[blk][bz], 1);
        atomicAdd(&hist[blk][bw], 1);
    }
    __syncthreads();

    for (int i = t; i < 64 * C_; i += 256) {
        int j = i / C_, c = i % C_;
        g_adjusted[((size_t)(b * C_ + c) * 64 + strip) * 64 + j] =
            (float)hist[j][c] * (1.0f / 64.0f);
    }
}

// ---------------------------------------------------------------------------
// Kernel 2: R2 core (pr[16] in regs, attn in smem, __ldcs/__stcs) with the
// tile loop unrolled x4: four front-batched LDG.128 per group (MLP_p1 = 4).
// ---------------------------------------------------------------------------
#define CPP 8
#define TPC 128

__global__ __launch_bounds__(256, 2) void modulate_kernel(
    const float* __restrict__ x,
    const float* __restrict__ attn,
    float* __restrict__ out_y,
    float* __restrict__ out_c)
{
    const int bc   = blockIdx.x >> 3;      // 0..151
    const int q    = blockIdx.x & 7;
    const int tid  = threadIdx.x;
    const int mgrp = tid >> 6;             // 0..3
    const int quad = tid & 63;
    const int py   = quad >> 2;            // 0..15
    const int px0  = (quad & 3) << 2;      // 0,4,8,12

    __shared__ float4 sm_attn[TPC * 4];    // 8KB

    const float* adjc = g_adjusted + (size_t)bc * 4096;
    float4 pr[16];
    #pragma unroll
    for (int pi = 0; pi < 4; pi++)
        #pragma unroll
        for (int pj = 0; pj < 4; pj++)
            pr[pi * 4 + pj] =
                *(const float4*)(adjc + (pi * 16 + py) * 64 + pj * 16 + px0);

    const float4* src = (const float4*)(attn + (size_t)bc * 1024 * 16) + q * TPC * 4;
    for (int i = tid; i < TPC * 4; i += 256) sm_attn[i] = src[i];
    __syncthreads();

    const float* xp = x + (size_t)bc * PLANE;
    float*       yp = out_y + (size_t)bc * PLANE;
    float*       cp = out_c + (size_t)bc * PLANE;

    const int mh = q * 4 + mgrp;           // tile row (0..31)
    const int h  = mh * 16 + py;
    const size_t base = (size_t)h * W_ + px0;
    const int mlbase = mgrp * 32;

    #pragma unroll 1
    for (int ib = 0; ib < 32; ib += 4) {
        const size_t pix0 = base + (size_t)ib * 16;

        // 4 front-batched loads (MLP_p1 = 4)
        float4 xq0 = __ldcs((const float4*)(xp + pix0));
        float4 xq1 = __ldcs((const float4*)(xp + pix0 + 16));
        float4 xq2 = __ldcs((const float4*)(xp + pix0 + 32));
        float4 xq3 = __ldcs((const float4*)(xp + pix0 + 48));

        #pragma unroll
        for (int j = 0; j < 4; j++) {
            const float4 cur = (j == 0) ? xq0 : (j == 1) ? xq1 : (j == 2) ? xq2 : xq3;
            const size_t pix = pix0 + (size_t)j * 16;
            const int mloc = mlbase + ib + j;

            float4 c4 = make_float4(0.f, 0.f, 0.f, 0.f);
            #pragma unroll
            for (int g = 0; g < 4; g++) {
                float4 a4 = sm_attn[mloc * 4 + g];
                c4.x = fmaf(a4.x, pr[g*4+0].x, c4.x);
                c4.y = fmaf(a4.x, pr[g*4+0].y, c4.y);
                c4.z = fmaf(a4.x, pr[g*4+0].z, c4.z);
                c4.w = fmaf(a4.x, pr[g*4+0].w, c4.w);
                c4.x = fmaf(a4.y, pr[g*4+1].x, c4.x);
                c4.y = fmaf(a4.y, pr[g*4+1].y, c4.y);
                c4.z = fmaf(a4.y, pr[g*4+1].z, c4.z);
                c4.w = fmaf(a4.y, pr[g*4+1].w, c4.w);
                c4.x = fmaf(a4.z, pr[g*4+2].x, c4.x);
                c4.y = fmaf(a4.z, pr[g*4+2].y, c4.y);
                c4.z = fmaf(a4.z, pr[g*4+2].z, c4.z);
                c4.w = fmaf(a4.z, pr[g*4+2].w, c4.w);
                c4.x = fmaf(a4.w, pr[g*4+3].x, c4.x);
                c4.y = fmaf(a4.w, pr[g*4+3].y, c4.y);
                c4.z = fmaf(a4.w, pr[g*4+3].z, c4.z);
                c4.w = fmaf(a4.w, pr[g*4+3].w, c4.w);
            }

            float4 y2;
            float tx = 1.f + c4.x; y2.x = cur.x * tx * tx;
            float ty = 1.f + c4.y; y2.y = cur.y * ty * ty;
            float tz = 1.f + c4.z; y2.z = cur.z * tz * tz;
            float tw = 1.f + c4.w; y2.w = cur.w * tw * tw;

            __stcs((float4*)(yp + pix), y2);
            __stcs((float4*)(cp + pix), c4);
        }
    }
}

extern "C" void kernel_launch(void* const* d_in, const int* in_sizes, int n_in,
                              void* d_out, int out_size)
{
    const float* x    = (const float*)d_in[0];
    const float* attn = (const float*)d_in[1];
    float* out_y = (float*)d_out;
    float* out_c = (float*)d_out + (size_t)BC * PLANE;

    dim3 g1(64, 8);
    argmax_pool_kernel<<<g1, 256>>>(x);
    modulate_kernel<<<BC * CPP, 256>>>(x, attn, out_y, out_c);
}